// round 14
// baseline (speedup 1.0000x reference)
#include <cuda_runtime.h>
#include <math.h>

#define BB 8
#define NN 4096
#define DD 1024
#define HH 1792

#define GRID 296          // 148 SMs x 2 CTAs (forced by launch_bounds)
#define TPB 256
#define NCHU 256          // h-chunks in phase B
#define HPERU 7           // 256 * 7 = 1792
#define CGRP 8            // partials per phase-C block
#define BPB 37            // blocks per batch in phases A and D (296/8)

// Scratch (allocation-free contract): __device__ globals, zero at load.
// All sync vars are MONOTONIC across runs (epoch-relative targets);
// accumulators are double-buffered: run e uses buf=e&1, zeroes buf^1.
__device__ float g_xbar2[2][BB * DD];
__device__ float g_u2[2][BB * DD];
__device__ float g_c2[2][BB];
__device__ float g_upart[NCHU][BB * DD];   // overwritten each run (flag-ordered)
__device__ unsigned g_flag[NCHU];          // B->C per-chunk (holds epoch+1)
__device__ unsigned g_cnt[BB];             // C->D per-batch strip counters
__device__ unsigned g_ccnt;                // B->D c-completion counter
__device__ unsigned g_bar;                 // grid barrier (monotonic)

// ---------------------------------------------------------------------------
// Software grid barrier (absolute target). Safe: all GRID blocks co-resident.
__device__ __forceinline__ void gridbar(unsigned target) {
    __syncthreads();
    if (threadIdx.x == 0) {
        __threadfence();
        atomicAdd(&g_bar, 1u);
        unsigned v;
        do {
            asm volatile("ld.volatile.global.u32 %0, [%1];"
                         : "=r"(v) : "l"(&g_bar));
            if (v < target) __nanosleep(64);
        } while (v < target);
        __threadfence();
    }
    __syncthreads();
}

__device__ __forceinline__ unsigned vload(const unsigned* p) {
    unsigned v;
    asm volatile("ld.volatile.global.u32 %0, [%1];" : "=r"(v) : "l"(p));
    return v;
}

// ---------------------------------------------------------------------------
__global__ void __launch_bounds__(TPB, 2)
k_main(const float* __restrict__ x,  const float* __restrict__ Wq,
       const float* __restrict__ bq, const float* __restrict__ Wk,
       const float* __restrict__ bk, float* __restrict__ out) {
    const int t = threadIdx.x;
    const int blk = blockIdx.x;
    const int warp = t >> 5, lane = t & 31;
    __shared__ float s_kb[HPERU][BB];
    __shared__ unsigned s_e;

    // Epoch: exactly one gridbar per run => g_bar in [e*GRID, e*GRID+GRID-1]
    // at any point before this block's own arrival. Previous runs fully
    // complete (kernel boundary), so e = g_bar / GRID.
    if (t == 0) s_e = vload(&g_bar) / GRID;
    __syncthreads();
    const unsigned e = s_e;
    const int buf = (int)(e & 1u);
    float* xbar = g_xbar2[buf];
    float* u    = g_u2[buf];
    float* cvec = g_c2[buf];

    // Zero next run's accumulators (prev run's reads done at kernel boundary).
    {
        const int gid = blk * TPB + t;
        if (gid < BB * DD) { g_xbar2[buf ^ 1][gid] = 0.f;
                             g_u2[buf ^ 1][gid]    = 0.f; }
        if (gid < BB)        g_c2[buf ^ 1][gid]    = 0.f;
    }

    // Block's row range for phases A and D.
    const int myb = blk / BPB;                 // 0..7
    const int myc = blk % BPB;
    const int n0 = (myc * NN) / BPB;
    const int n1 = ((myc + 1) * NN) / BPB;

    // ===== Phase A: xbar[b,d] = (1/N) sum_n x[b,n,d] ======================
    {
        const float4* xp = (const float4*)(x + (size_t)myb * NN * DD);
        float4 acc = make_float4(0.f, 0.f, 0.f, 0.f);
        int n = n0;
        for (; n + 8 <= n1; n += 8) {
            #pragma unroll
            for (int j = 0; j < 8; j++) {
                float4 v = xp[(size_t)(n + j) * (DD / 4) + t];
                acc.x += v.x; acc.y += v.y; acc.z += v.z; acc.w += v.w;
            }
        }
        for (; n < n1; n++) {
            float4 v = xp[(size_t)n * (DD / 4) + t];
            acc.x += v.x; acc.y += v.y; acc.z += v.z; acc.w += v.w;
        }
        const float invN = 1.0f / (float)NN;
        float* dst = xbar + myb * DD + t * 4;
        atomicAdd(dst + 0, acc.x * invN);
        atomicAdd(dst + 1, acc.y * invN);
        atomicAdd(dst + 2, acc.z * invN);
        atomicAdd(dst + 3, acc.w * invN);
    }
    gridbar((e + 1u) * GRID);   // the one inherent all-reduce barrier

    // ===== Phase B: kbar chunk (smem) + upart; flag + ccnt release ========
    if (blk < NCHU) {
        const int hbase = blk * HPERU;
        if (warp < HPERU) {
            const int h = hbase + warp;
            const float4* wk = (const float4*)(Wk + (size_t)h * DD);
            float4 wreg[8];
            #pragma unroll
            for (int i = 0; i < 8; i++) wreg[i] = wk[i * 32 + lane];

            float acc[BB];
            #pragma unroll
            for (int b = 0; b < BB; b++) {
                const float4* xb = (const float4*)(xbar + b * DD);
                float s = 0.f;
                #pragma unroll
                for (int i = 0; i < 8; i++) {
                    float4 xv = xb[i * 32 + lane];
                    s += wreg[i].x * xv.x + wreg[i].y * xv.y
                       + wreg[i].z * xv.z + wreg[i].w * xv.w;
                }
                acc[b] = s;
            }
            #pragma unroll
            for (int b = 0; b < BB; b++)
                #pragma unroll
                for (int o = 16; o > 0; o >>= 1)
                    acc[b] += __shfl_xor_sync(0xffffffffu, acc[b], o);

            if (lane < BB) {
                const float kb = acc[lane] + bk[h];  // lane b = kbar[b][h]
                s_kb[warp][lane] = kb;
                atomicAdd(&cvec[lane], bq[h] * kb);
            }
        }
        __syncthreads();

        // Preload all 7 Wq rows (MLP=7), then pure-FMA accumulation.
        float4 wq[HPERU];
        #pragma unroll
        for (int hh = 0; hh < HPERU; hh++)
            wq[hh] = ((const float4*)(Wq + (size_t)(hbase + hh) * DD))[t];

        float4 acc[BB];
        #pragma unroll
        for (int b = 0; b < BB; b++) acc[b] = make_float4(0.f, 0.f, 0.f, 0.f);
        #pragma unroll
        for (int hh = 0; hh < HPERU; hh++) {
            #pragma unroll
            for (int b = 0; b < BB; b++) {
                const float kb = s_kb[hh][b];
                acc[b].x = fmaf(wq[hh].x, kb, acc[b].x);
                acc[b].y = fmaf(wq[hh].y, kb, acc[b].y);
                acc[b].z = fmaf(wq[hh].z, kb, acc[b].z);
                acc[b].w = fmaf(wq[hh].w, kb, acc[b].w);
            }
        }
        float4* dst = (float4*)(g_upart[blk]);
        #pragma unroll
        for (int b = 0; b < BB; b++) dst[b * (DD / 4) + t] = acc[b];

        __threadfence();
        __syncthreads();
        if (t == 0) {
            atomicExch(&g_flag[blk], e + 1u);   // upart ready
            atomicAdd(&g_ccnt, 1u);             // c contribution done
        }
    }

    // ===== Phase C: strip ib of u = sum of 8 producers (flag-synced) ======
    if (blk < NCHU) {                       // 256 blocks: 8 strips x 32 groups
        const int ib = blk & 7;
        const int cbase = (blk >> 3) * CGRP;

        if (t < CGRP) {
            const unsigned* f = g_flag + cbase + t;
            while (vload(f) < e + 1u) __nanosleep(64);
        }
        __syncthreads();
        __threadfence();                    // acquire producers' stores

        const int f4 = ib * 256 + t;
        float4 s = make_float4(0.f, 0.f, 0.f, 0.f);
        #pragma unroll
        for (int j = 0; j < CGRP; j++) {
            float4 v = ((const float4*)(g_upart[cbase + j]))[f4];
            s.x += v.x; s.y += v.y; s.z += v.z; s.w += v.w;
        }
        float* dst = u + f4 * 4;
        atomicAdd(dst + 0, s.x);
        atomicAdd(dst + 1, s.y);
        atomicAdd(dst + 2, s.z);
        atomicAdd(dst + 3, s.w);

        __threadfence();
        __syncthreads();
        if (t == 0) atomicAdd(&g_cnt[ib], 1u);  // strip contribution done
    }

    // ===== Phase D: score own rows once batch myb's u and c are ready =====
    {
        if (t == 0) {                        // u strip myb: 32 contributions
            const unsigned* p = &g_cnt[myb];
            while (vload(p) < 32u * (e + 1u)) __nanosleep(64);
        } else if (t == 32) {                // c: all 256 B blocks
            while (vload(&g_ccnt) < 256u * (e + 1u)) __nanosleep(64);
        }
        __syncthreads();
        __threadfence();                     // acquire u and c

        const float scale = rsqrtf((float)HH);
        const float cb = cvec[myb];
        const float4* up = (const float4*)(u + myb * DD);
        const float* xbase = x + (size_t)myb * NN * DD;
        float* obase = out + myb * NN;

        for (int n = n0 + warp; n < n1; n += 8) {
            const float4* xp = (const float4*)(xbase + (size_t)n * DD);
            float4 v[8];
            #pragma unroll
            for (int i = 0; i < 8; i++) v[i] = xp[i * 32 + lane];
            float acc = 0.f;
            #pragma unroll
            for (int i = 0; i < 8; i++) {
                const float4 uv = up[i * 32 + lane];
                acc += v[i].x * uv.x + v[i].y * uv.y
                     + v[i].z * uv.z + v[i].w * uv.w;
            }
            #pragma unroll
            for (int o = 16; o > 0; o >>= 1)
                acc += __shfl_down_sync(0xffffffffu, acc, o);
            if (lane == 0) obase[n] = scale * (acc + cb);
        }
    }
}

// ---------------------------------------------------------------------------
extern "C" void kernel_launch(void* const* d_in, const int* in_sizes, int n_in,
                              void* d_out, int out_size) {
    const float* x  = (const float*)d_in[0];   // [B, N, D] f32
    const float* Wq = (const float*)d_in[1];   // [H, D]    f32
    const float* bq = (const float*)d_in[2];   // [H]       f32
    const float* Wk = (const float*)d_in[3];   // [H, D]    f32
    const float* bk = (const float*)d_in[4];   // [H]       f32
    float* out = (float*)d_out;                // [B, N]    f32

    k_main<<<GRID, TPB>>>(x, Wq, bq, Wk, bk, out);
}

// round 15
// speedup vs baseline: 1.1538x; 1.1538x over previous
#include <cuda_runtime.h>
#include <math.h>

#define BB 8
#define NN 4096
#define DD 1024
#define HH 1792

#define GRID 296          // 148 SMs x 2 CTAs (forced by launch_bounds)
#define TPB 256
#define NCHU 256          // h-chunks in phase B
#define HPERU 7           // 256 * 7 = 1792
#define CGRP 8            // partials per phase-C block
#define BLKS_PER_B 37     // 296 / 8 blocks per batch in phase A

// Scratch (allocation-free contract): __device__ globals, zero at load.
// Sync vars are MONOTONIC across runs (2 barrier arrivals per block per run,
// so epoch e = g_bar / (2*GRID) at kernel entry). Accumulators are
// double-buffered: run e uses buf = e&1 and zeroes buf^1 for the next run.
__device__ float g_xbar2[2][BB * DD];
__device__ float g_u2[2][BB * DD];
__device__ float g_c2[2][BB];
__device__ float g_upart[NCHU][BB * DD];   // overwritten each run (flag-ordered)
__device__ unsigned g_flag[NCHU];          // B->C per-chunk (holds epoch+1)
__device__ unsigned g_bar;                 // grid barrier (monotonic)

// ---------------------------------------------------------------------------
// Software grid barrier (absolute target). Safe: all GRID blocks co-resident.
__device__ __forceinline__ void gridbar(unsigned target) {
    __syncthreads();
    if (threadIdx.x == 0) {
        __threadfence();
        atomicAdd(&g_bar, 1u);
        unsigned v;
        do {
            asm volatile("ld.volatile.global.u32 %0, [%1];"
                         : "=r"(v) : "l"(&g_bar));
            if (v < target) __nanosleep(64);
        } while (v < target);
        __threadfence();
    }
    __syncthreads();
}

__device__ __forceinline__ unsigned vload(const unsigned* p) {
    unsigned v;
    asm volatile("ld.volatile.global.u32 %0, [%1];" : "=r"(v) : "l"(p));
    return v;
}

// ---------------------------------------------------------------------------
__global__ void __launch_bounds__(TPB, 2)
k_main(const float* __restrict__ x,  const float* __restrict__ Wq,
       const float* __restrict__ bq, const float* __restrict__ Wk,
       const float* __restrict__ bk, float* __restrict__ out) {
    const int t = threadIdx.x;
    const int blk = blockIdx.x;
    const int warp = t >> 5, lane = t & 31;
    __shared__ float s_kb[HPERU][BB];
    __shared__ unsigned s_e;

    // Epoch: 2 arrivals/block/run. Before this block's first arrival,
    // g_bar in [2e*GRID, 2e*GRID + GRID - 1]  =>  e = g_bar / (2*GRID).
    if (t == 0) s_e = vload(&g_bar) / (2u * GRID);
    __syncthreads();
    const unsigned e = s_e;
    const int buf = (int)(e & 1u);
    float* xbar = g_xbar2[buf];
    float* u    = g_u2[buf];
    float* cvec = g_c2[buf];

    // Zero next run's accumulators (prev run's reads ended at its boundary).
    {
        const int gid = blk * TPB + t;
        if (gid < BB * DD) { g_xbar2[buf ^ 1][gid] = 0.f;
                             g_u2[buf ^ 1][gid]    = 0.f; }
        if (gid < BB)        g_c2[buf ^ 1][gid]    = 0.f;
    }

    // ===== Phase A: xbar[b,d] = (1/N) sum_n x[b,n,d]  (R13 verbatim) =====
    {
        const int b = blk / BLKS_PER_B;            // 0..7
        const int c = blk % BLKS_PER_B;
        const int n0 = (c * NN) / BLKS_PER_B;
        const int n1 = ((c + 1) * NN) / BLKS_PER_B;
        const float4* xp = (const float4*)(x + (size_t)b * NN * DD);

        float4 acc = make_float4(0.f, 0.f, 0.f, 0.f);
        int n = n0;
        for (; n + 8 <= n1; n += 8) {
            #pragma unroll
            for (int j = 0; j < 8; j++) {
                float4 v = xp[(size_t)(n + j) * (DD / 4) + t];
                acc.x += v.x; acc.y += v.y; acc.z += v.z; acc.w += v.w;
            }
        }
        for (; n < n1; n++) {
            float4 v = xp[(size_t)n * (DD / 4) + t];
            acc.x += v.x; acc.y += v.y; acc.z += v.z; acc.w += v.w;
        }
        const float invN = 1.0f / (float)NN;
        float* dst = xbar + b * DD + t * 4;
        atomicAdd(dst + 0, acc.x * invN);
        atomicAdd(dst + 1, acc.y * invN);
        atomicAdd(dst + 2, acc.z * invN);
        atomicAdd(dst + 3, acc.w * invN);
    }
    gridbar((2u * e + 1u) * GRID);

    // ===== Phase B: kbar chunk (smem) + upart; epoch flag release =========
    if (blk < NCHU) {
        const int hbase = blk * HPERU;
        if (warp < HPERU) {
            const int h = hbase + warp;
            const float4* wk = (const float4*)(Wk + (size_t)h * DD);
            float4 wreg[8];
            #pragma unroll
            for (int i = 0; i < 8; i++) wreg[i] = wk[i * 32 + lane];

            float acc[BB];
            #pragma unroll
            for (int b = 0; b < BB; b++) {
                const float4* xb = (const float4*)(xbar + b * DD);
                float s = 0.f;
                #pragma unroll
                for (int i = 0; i < 8; i++) {
                    float4 xv = xb[i * 32 + lane];
                    s += wreg[i].x * xv.x + wreg[i].y * xv.y
                       + wreg[i].z * xv.z + wreg[i].w * xv.w;
                }
                acc[b] = s;
            }
            #pragma unroll
            for (int b = 0; b < BB; b++)
                #pragma unroll
                for (int o = 16; o > 0; o >>= 1)
                    acc[b] += __shfl_xor_sync(0xffffffffu, acc[b], o);

            if (lane < BB) {
                const float kb = acc[lane] + bk[h];  // lane b = kbar[b][h]
                s_kb[warp][lane] = kb;
                atomicAdd(&cvec[lane], bq[h] * kb);
            }
        }
        __syncthreads();

        // Preload all 7 Wq rows (MLP=7), then pure-FMA accumulation.
        float4 wq[HPERU];
        #pragma unroll
        for (int hh = 0; hh < HPERU; hh++)
            wq[hh] = ((const float4*)(Wq + (size_t)(hbase + hh) * DD))[t];

        float4 acc[BB];
        #pragma unroll
        for (int b = 0; b < BB; b++) acc[b] = make_float4(0.f, 0.f, 0.f, 0.f);
        #pragma unroll
        for (int hh = 0; hh < HPERU; hh++) {
            #pragma unroll
            for (int b = 0; b < BB; b++) {
                const float kb = s_kb[hh][b];
                acc[b].x = fmaf(wq[hh].x, kb, acc[b].x);
                acc[b].y = fmaf(wq[hh].y, kb, acc[b].y);
                acc[b].z = fmaf(wq[hh].z, kb, acc[b].z);
                acc[b].w = fmaf(wq[hh].w, kb, acc[b].w);
            }
        }
        float4* dst = (float4*)(g_upart[blk]);
        #pragma unroll
        for (int b = 0; b < BB; b++) dst[b * (DD / 4) + t] = acc[b];

        __threadfence();
        __syncthreads();
        if (t == 0) atomicExch(&g_flag[blk], e + 1u);
    }

    // ===== Phase C: u = sum of my 8 producers' upart (flag-synced) ========
    if (blk < NCHU) {                       // 256 blocks: 8 strips x 32 groups
        const int ib = blk & 7;
        const int cbase = (blk >> 3) * CGRP;

        if (t < CGRP) {
            const unsigned* f = g_flag + cbase + t;
            while (vload(f) < e + 1u) __nanosleep(64);
        }
        __syncthreads();
        __threadfence();                    // acquire producers' stores

        const int f4 = ib * 256 + t;
        float4 s = make_float4(0.f, 0.f, 0.f, 0.f);
        #pragma unroll
        for (int j = 0; j < CGRP; j++) {
            float4 v = ((const float4*)(g_upart[cbase + j]))[f4];
            s.x += v.x; s.y += v.y; s.z += v.z; s.w += v.w;
        }
        float* dst = u + f4 * 4;
        atomicAdd(dst + 0, s.x);
        atomicAdd(dst + 1, s.y);
        atomicAdd(dst + 2, s.z);
        atomicAdd(dst + 3, s.w);
    }
    gridbar((2u * e + 2u) * GRID);

    // ===== Phase D: grid-strided scores (R13 verbatim) ====================
    {
        const float scale = rsqrtf((float)HH);
        const int wglobal = blk * 8 + warp;          // 0..2367
        for (int r = wglobal; r < BB * NN; r += GRID * 8) {
            const int b = r >> 12;                   // N = 4096
            const float4* xp = (const float4*)(x + (size_t)r * DD);
            const float4* up = (const float4*)(u + b * DD);
            float acc = 0.f;
            #pragma unroll
            for (int i = 0; i < 8; i++) {
                float4 xv = xp[i * 32 + lane];
                float4 uv = up[i * 32 + lane];
                acc += xv.x * uv.x + xv.y * uv.y + xv.z * uv.z + xv.w * uv.w;
            }
            #pragma unroll
            for (int o = 16; o > 0; o >>= 1)
                acc += __shfl_down_sync(0xffffffffu, acc, o);
            if (lane == 0) out[r] = scale * (acc + cvec[b]);
        }
    }
}

// ---------------------------------------------------------------------------
extern "C" void kernel_launch(void* const* d_in, const int* in_sizes, int n_in,
                              void* d_out, int out_size) {
    const float* x  = (const float*)d_in[0];   // [B, N, D] f32
    const float* Wq = (const float*)d_in[1];   // [H, D]    f32
    const float* bq = (const float*)d_in[2];   // [H]       f32
    const float* Wk = (const float*)d_in[3];   // [H, D]    f32
    const float* bk = (const float*)d_in[4];   // [H]       f32
    float* out = (float*)d_out;                // [B, N]    f32

    k_main<<<GRID, TPB>>>(x, Wq, bq, Wk, bk, out);
}